// round 1
// baseline (speedup 1.0000x reference)
#include <cuda_runtime.h>

// Problem constants (fixed by the reference: N=8192 points, B=2048 models)
#define N_PTS        8192
#define N_MODELS     2048
#define THREADS      256          // models per block (thread = model)
#define PTS_PER_BLK  256          // points per chunk
#define N_CHUNKS     (N_PTS / PTS_PER_BLK)      // 32
#define N_MBLK       (N_MODELS / THREADS)       // 8
#define INL_TH_SQ    4.0f

// Scratch (no cudaMalloc allowed): deterministic partial sums + best index
__device__ float g_part[N_CHUNKS][N_MODELS];
__device__ int   g_best_idx;

// ---------------------------------------------------------------------------
// Kernel 1: partial scores. Each thread owns one model (12 regs), iterates a
// 256-point tile held in shared memory. All lanes of a warp read the same
// point each iteration -> LDS broadcast, conflict-free. Fixed summation order
// per thread => deterministic.
// ---------------------------------------------------------------------------
__global__ __launch_bounds__(THREADS)
void p3p_score_kernel(const float* __restrict__ X,       // (N,4) homogeneous
                      const float* __restrict__ x,       // (N,3) homogeneous
                      const float* __restrict__ models)  // (B,3,4)
{
    __shared__ float4 sP[PTS_PER_BLK];   // {Xx, Xy, Xz, xx}
    __shared__ float  sY[PTS_PER_BLK];   // xy

    const int t     = threadIdx.x;
    const int mblk  = blockIdx.x;        // 0..7
    const int chunk = blockIdx.y;        // 0..31
    const int n0    = chunk * PTS_PER_BLK;

    // Cooperative point-tile load (one point per thread)
    {
        const int n = n0 + t;
        float4 X4 = *reinterpret_cast<const float4*>(X + 4 * n);  // w == 1
        float xx = x[3 * n + 0];
        float xy = x[3 * n + 1];
        sP[t] = make_float4(X4.x, X4.y, X4.z, xx);
        sY[t] = xy;
    }
    __syncthreads();

    const int m = mblk * THREADS + t;
    const float* M = models + 12 * m;
    const float m00 = M[0],  m01 = M[1],  m02 = M[2],  m03 = M[3];
    const float m10 = M[4],  m11 = M[5],  m12 = M[6],  m13 = M[7];
    const float m20 = M[8],  m21 = M[9],  m22 = M[10], m23 = M[11];

    float acc = 0.0f;
    #pragma unroll 8
    for (int i = 0; i < PTS_PER_BLK; ++i) {
        const float4 p  = sP[i];
        const float  xy = sY[i];
        // projected = M @ [X;1]
        const float pz = fmaf(m20, p.x, fmaf(m21, p.y, fmaf(m22, p.z, m23)));
        const float px = fmaf(m00, p.x, fmaf(m01, p.y, fmaf(m02, p.z, m03)));
        const float py = fmaf(m10, p.x, fmaf(m11, p.y, fmaf(m12, p.z, m13)));
        const float inv = 1.0f / pz;
        const float dx = fmaf(px, inv, -p.w);
        const float dy = fmaf(py, inv, -xy);
        const float d2 = fmaf(dx, dx, dy * dy);
        // clip(d2, 0, 4), then force 4 where chirality fails (pz <= 0)
        const float s  = (pz > 0.0f) ? fminf(d2, INL_TH_SQ) : INL_TH_SQ;
        acc += s;
    }
    g_part[chunk][m] = acc;
}

// ---------------------------------------------------------------------------
// Kernel 2: finish scores (fixed-order sum over chunks) + argmin over 2048
// models (tie-break: lowest index, matching jnp.argmin). Writes best model
// (out[0..11]) and best score (out[12 + N_PTS]).
// ---------------------------------------------------------------------------
__global__ __launch_bounds__(1024)
void p3p_reduce_kernel(const float* __restrict__ models, float* __restrict__ out)
{
    __shared__ float sv[1024];
    __shared__ int   si[1024];
    __shared__ int   s_best;

    const int t = threadIdx.x;

    // Each thread finishes two models' scores, keeps the better one
    float bestv = 3.4e38f;
    int   besti = 0;
    #pragma unroll
    for (int r = 0; r < 2; ++r) {
        const int mdl = t + r * 1024;
        float s = 0.0f;
        #pragma unroll
        for (int c = 0; c < N_CHUNKS; ++c)
            s += g_part[c][mdl];
        if (s < bestv || (s == bestv && mdl < besti)) { bestv = s; besti = mdl; }
    }
    sv[t] = bestv;
    si[t] = besti;
    __syncthreads();

    for (int stride = 512; stride > 0; stride >>= 1) {
        if (t < stride) {
            const float ov = sv[t + stride];
            const int   oi = si[t + stride];
            if (ov < sv[t] || (ov == sv[t] && oi < si[t])) { sv[t] = ov; si[t] = oi; }
        }
        __syncthreads();
    }
    if (t == 0) {
        s_best = si[0];
        g_best_idx = si[0];
        out[12 + N_PTS] = sv[0];
    }
    __syncthreads();
    if (t < 12)
        out[t] = models[12 * s_best + t];
}

// ---------------------------------------------------------------------------
// Kernel 3: inlier mask for the winning model only.
// inlier = (pz > 0) && (d2 < 4.0)   (strict, on the unclipped error)
// ---------------------------------------------------------------------------
__global__ __launch_bounds__(256)
void p3p_inlier_kernel(const float* __restrict__ X,
                       const float* __restrict__ x,
                       const float* __restrict__ models,
                       float* __restrict__ out)
{
    const int n = blockIdx.x * blockDim.x + threadIdx.x;
    const int bi = g_best_idx;
    const float* M = models + 12 * bi;

    float4 X4 = *reinterpret_cast<const float4*>(X + 4 * n);
    const float xx = x[3 * n + 0];
    const float xy = x[3 * n + 1];

    const float pz = fmaf(M[8], X4.x, fmaf(M[9],  X4.y, fmaf(M[10], X4.z, M[11])));
    const float px = fmaf(M[0], X4.x, fmaf(M[1],  X4.y, fmaf(M[2],  X4.z, M[3])));
    const float py = fmaf(M[4], X4.x, fmaf(M[5],  X4.y, fmaf(M[6],  X4.z, M[7])));
    const float inv = 1.0f / pz;
    const float dx = fmaf(px, inv, -xx);
    const float dy = fmaf(py, inv, -xy);
    const float d2 = fmaf(dx, dx, dy * dy);

    out[12 + n] = (pz > 0.0f && d2 < INL_TH_SQ) ? 1.0f : 0.0f;
}

// ---------------------------------------------------------------------------
extern "C" void kernel_launch(void* const* d_in, const int* in_sizes, int n_in,
                              void* d_out, int out_size)
{
    const float* X      = (const float*)d_in[0];   // (8192, 4)
    const float* x      = (const float*)d_in[1];   // (8192, 3)
    const float* models = (const float*)d_in[2];   // (2048, 3, 4)
    float* out = (float*)d_out;                    // 12 + 8192 + 1 = 8205 floats

    (void)in_sizes; (void)n_in; (void)out_size;

    dim3 grid1(N_MBLK, N_CHUNKS);
    p3p_score_kernel<<<grid1, THREADS>>>(X, x, models);
    p3p_reduce_kernel<<<1, 1024>>>(models, out);
    p3p_inlier_kernel<<<N_PTS / 256, 256>>>(X, x, models, out);
}

// round 2
// speedup vs baseline: 1.1976x; 1.1976x over previous
#include <cuda_runtime.h>

// Problem constants (fixed by the reference: N=8192 points, B=2048 models)
#define N_PTS        8192
#define N_MODELS     2048
#define THREADS      256          // models per block (thread = model)
#define TILE         128          // points per chunk
#define PAIRS        (TILE / 2)   // 64 point-pairs per chunk
#define N_CHUNKS     (N_PTS / TILE)             // 64
#define N_MBLK       (N_MODELS / THREADS)       // 8
#define INL_TH_SQ    4.0f
#define BIG_GATE     1e18f

// Scratch (no cudaMalloc allowed): deterministic partial "gain" sums + best idx
__device__ float g_part[N_CHUNKS][N_MODELS];

// ---------------------------------------------------------------------------
// f32x2 packed-math helpers (PTX ISA 8.6, sm_100+). One instruction = 2 FMAs.
// ---------------------------------------------------------------------------
typedef unsigned long long u64;

__device__ __forceinline__ u64 fma2(u64 a, u64 b, u64 c) {
    u64 d; asm("fma.rn.f32x2 %0, %1, %2, %3;" : "=l"(d) : "l"(a), "l"(b), "l"(c));
    return d;
}
__device__ __forceinline__ u64 mul2(u64 a, u64 b) {
    u64 d; asm("mul.rn.f32x2 %0, %1, %2;" : "=l"(d) : "l"(a), "l"(b));
    return d;
}
__device__ __forceinline__ u64 pack2(float lo, float hi) {
    u64 d; asm("mov.b64 %0, {%1, %2};" : "=l"(d) : "f"(lo), "f"(hi));
    return d;
}
__device__ __forceinline__ void unpack2(u64 v, float& lo, float& hi) {
    asm("mov.b64 {%0, %1}, %2;" : "=f"(lo), "=f"(hi) : "l"(v));
}
__device__ __forceinline__ float rcp_approx(float x) {
    float y; asm("rcp.approx.f32 %0, %1;" : "=f"(y) : "f"(x));
    return y;
}

// ---------------------------------------------------------------------------
// Kernel 1: per-(chunk, model) "gain" partial sums.
// Thread = model; inner loop walks 64 point-PAIRS held packed in shared.
// All lanes read the same pair -> LDS broadcast. Gain formulation:
//   gain = max( min(4 - d2, BIG*pz), 0 )     (==  4 - clip_score, gated by pz>0)
// so score(model) = 4*N - sum(gain). Branch-free, select-free, fully packed.
// ---------------------------------------------------------------------------
__global__ __launch_bounds__(THREADS)
void p3p_score_kernel(const float* __restrict__ X,       // (N,4) homogeneous
                      const float* __restrict__ x,       // (N,3) homogeneous
                      const float* __restrict__ models)  // (B,3,4)
{
    // Pair-packed tiles: each u64 holds {pt0, pt1} floats, ready as f32x2.
    __shared__ ulonglong2 sA[PAIRS];   // .x = {Xx0,Xx1}   .y = {Xy0,Xy1}
    __shared__ ulonglong2 sB[PAIRS];   // .x = {Xz0,Xz1}   .y = {-xx0,-xx1}
    __shared__ u64        sC[PAIRS];   //      {-xy0,-xy1}

    const int t     = threadIdx.x;
    const int mblk  = blockIdx.x;        // 0..7
    const int chunk = blockIdx.y;        // 0..63
    const int n0    = chunk * TILE;

    // Cooperative tile load: threads 0..127 each place one point into the
    // packed layout (scalar STS, trivial cost, once per block).
    if (t < TILE) {
        const int n = n0 + t;
        const int j = t >> 1, h = t & 1;
        float4 X4 = *reinterpret_cast<const float4*>(X + 4 * n);  // w == 1
        const float xx = x[3 * n + 0];
        const float xy = x[3 * n + 1];
        float* fA = reinterpret_cast<float*>(sA);
        float* fB = reinterpret_cast<float*>(sB);
        float* fC = reinterpret_cast<float*>(sC);
        fA[4 * j + h]     = X4.x;
        fA[4 * j + 2 + h] = X4.y;
        fB[4 * j + h]     = X4.z;
        fB[4 * j + 2 + h] = -xx;
        fC[2 * j + h]     = -xy;
    }
    __syncthreads();

    // Model coefficients, broadcast-packed {m,m} once (12 reg pairs).
    const int m = mblk * THREADS + t;
    const float4 r0 = *reinterpret_cast<const float4*>(models + 12 * m + 0);
    const float4 r1 = *reinterpret_cast<const float4*>(models + 12 * m + 4);
    const float4 r2 = *reinterpret_cast<const float4*>(models + 12 * m + 8);
    const u64 M00 = pack2(r0.x, r0.x), M01 = pack2(r0.y, r0.y);
    const u64 M02 = pack2(r0.z, r0.z), M03 = pack2(r0.w, r0.w);
    const u64 M10 = pack2(r1.x, r1.x), M11 = pack2(r1.y, r1.y);
    const u64 M12 = pack2(r1.z, r1.z), M13 = pack2(r1.w, r1.w);
    const u64 M20 = pack2(r2.x, r2.x), M21 = pack2(r2.y, r2.y);
    const u64 M22 = pack2(r2.z, r2.z), M23 = pack2(r2.w, r2.w);
    const u64 NEG4_2 = pack2(-INL_TH_SQ, -INL_TH_SQ);
    const u64 BIG2   = pack2(BIG_GATE, BIG_GATE);

    float acc0 = 0.0f, acc1 = 0.0f;   // two chains: no FADD serialization

    #pragma unroll 8
    for (int j = 0; j < PAIRS; ++j) {
        const ulonglong2 A = sA[j];
        const ulonglong2 B = sB[j];
        const u64        C = sC[j];

        // projected = M @ [X;1]  (packed over the point pair)
        const u64 pz2 = fma2(M20, A.x, fma2(M21, A.y, fma2(M22, B.x, M23)));
        const u64 px2 = fma2(M00, A.x, fma2(M01, A.y, fma2(M02, B.x, M03)));
        const u64 py2 = fma2(M10, A.x, fma2(M11, A.y, fma2(M12, B.x, M13)));

        float zl, zh; unpack2(pz2, zl, zh);
        const u64 inv2 = pack2(rcp_approx(zl), rcp_approx(zh));

        const u64 dx2 = fma2(px2, inv2, B.y);       // px/pz - xx
        const u64 dy2 = fma2(py2, inv2, C);         // py/pz - xy
        const u64 t2  = fma2(dy2, dy2, NEG4_2);     // dy^2 - 4
        const u64 v2  = fma2(dx2, dx2, t2);         // dx^2 + dy^2 - 4
        const u64 c2  = mul2(pz2, BIG2);            // chirality gate

        float vl, vh, cl, ch;
        unpack2(v2, vl, vh);
        unpack2(c2, cl, ch);
        // gain = max(min(4-d2, BIG*pz), 0); NaN-safe (fminf drops NaN operand)
        acc0 += fmaxf(fminf(-vl, cl), 0.0f);
        acc1 += fmaxf(fminf(-vh, ch), 0.0f);
    }
    g_part[chunk][m] = acc0 + acc1;
}

// ---------------------------------------------------------------------------
// Kernel 2 (fused): finish gains (fixed-order sum), argmax gain == argmin
// score (tie -> lowest index, matching jnp.argmin), write best model + score,
// then compute the inlier mask for the winner in the same block.
// ---------------------------------------------------------------------------
__global__ __launch_bounds__(1024)
void p3p_finish_kernel(const float* __restrict__ X,
                       const float* __restrict__ x,
                       const float* __restrict__ models,
                       float* __restrict__ out)
{
    __shared__ float sv[1024];
    __shared__ int   si[1024];
    __shared__ int   s_best;

    const int t = threadIdx.x;

    // Each thread finishes two models' gains, keeps the better (larger) one
    float bestg = -1.0f;
    int   besti = 0;
    #pragma unroll
    for (int r = 0; r < 2; ++r) {
        const int mdl = t + r * 1024;
        float g = 0.0f;
        #pragma unroll
        for (int c = 0; c < N_CHUNKS; ++c)
            g += g_part[c][mdl];
        if (g > bestg || (g == bestg && mdl < besti)) { bestg = g; besti = mdl; }
    }
    sv[t] = bestg;
    si[t] = besti;
    __syncthreads();

    for (int stride = 512; stride > 0; stride >>= 1) {
        if (t < stride) {
            const float og = sv[t + stride];
            const int   oi = si[t + stride];
            if (og > sv[t] || (og == sv[t] && oi < si[t])) { sv[t] = og; si[t] = oi; }
        }
        __syncthreads();
    }
    if (t == 0) {
        s_best = si[0];
        out[12 + N_PTS] = INL_TH_SQ * (float)N_PTS - sv[0];   // score = 4N - gain
    }
    __syncthreads();

    const int bi = s_best;
    if (t < 12)
        out[t] = models[12 * bi + t];

    // Inlier mask for the winning model (exact division: no borderline flips)
    const float* M = models + 12 * bi;
    const float m00 = M[0], m01 = M[1], m02 = M[2],  m03 = M[3];
    const float m10 = M[4], m11 = M[5], m12 = M[6],  m13 = M[7];
    const float m20 = M[8], m21 = M[9], m22 = M[10], m23 = M[11];

    #pragma unroll
    for (int r = 0; r < N_PTS / 1024; ++r) {
        const int n = t + r * 1024;
        float4 X4 = *reinterpret_cast<const float4*>(X + 4 * n);
        const float xx = x[3 * n + 0];
        const float xy = x[3 * n + 1];
        const float pz = fmaf(m20, X4.x, fmaf(m21, X4.y, fmaf(m22, X4.z, m23)));
        const float px = fmaf(m00, X4.x, fmaf(m01, X4.y, fmaf(m02, X4.z, m03)));
        const float py = fmaf(m10, X4.x, fmaf(m11, X4.y, fmaf(m12, X4.z, m13)));
        const float inv = 1.0f / pz;                 // exact
        const float dx = fmaf(px, inv, -xx);
        const float dy = fmaf(py, inv, -xy);
        const float d2 = fmaf(dx, dx, dy * dy);
        out[12 + n] = (pz > 0.0f && d2 < INL_TH_SQ) ? 1.0f : 0.0f;
    }
}

// ---------------------------------------------------------------------------
extern "C" void kernel_launch(void* const* d_in, const int* in_sizes, int n_in,
                              void* d_out, int out_size)
{
    const float* X      = (const float*)d_in[0];   // (8192, 4)
    const float* x      = (const float*)d_in[1];   // (8192, 3)
    const float* models = (const float*)d_in[2];   // (2048, 3, 4)
    float* out = (float*)d_out;                    // 12 + 8192 + 1 floats

    (void)in_sizes; (void)n_in; (void)out_size;

    dim3 grid1(N_MBLK, N_CHUNKS);                  // 8 x 64 = 512 blocks
    p3p_score_kernel<<<grid1, THREADS>>>(X, x, models);
    p3p_finish_kernel<<<1, 1024>>>(X, x, models, out);
}

// round 3
// speedup vs baseline: 1.2627x; 1.0544x over previous
#include <cuda_runtime.h>

// Problem constants (fixed by the reference: N=8192 points, B=2048 models)
#define N_PTS        8192
#define N_MODELS     2048
#define THREADS      256          // models per block (thread = model)
#define TILE         128          // points per chunk
#define PAIRS        (TILE / 2)   // 64 point-pairs per chunk
#define N_CHUNKS     (N_PTS / TILE)             // 64
#define N_MBLK       (N_MODELS / THREADS)       // 8
#define INL_TH_SQ    4.0f
#define BIG_GATE     1e18f

// Scratch (no cudaMalloc allowed)
__device__ float g_part[N_CHUNKS][N_MODELS];   // per-(chunk,model) gain partials
__device__ float g_score[N_MODELS];            // per-model total gain
__device__ int   g_best_idx;

// ---------------------------------------------------------------------------
// f32x2 packed-math helpers (PTX ISA 8.6, sm_100+). One instruction = 2 FMAs.
// ---------------------------------------------------------------------------
typedef unsigned long long u64;

__device__ __forceinline__ u64 fma2(u64 a, u64 b, u64 c) {
    u64 d; asm("fma.rn.f32x2 %0, %1, %2, %3;" : "=l"(d) : "l"(a), "l"(b), "l"(c));
    return d;
}
__device__ __forceinline__ u64 mul2(u64 a, u64 b) {
    u64 d; asm("mul.rn.f32x2 %0, %1, %2;" : "=l"(d) : "l"(a), "l"(b));
    return d;
}
__device__ __forceinline__ u64 pack2(float lo, float hi) {
    u64 d; asm("mov.b64 %0, {%1, %2};" : "=l"(d) : "f"(lo), "f"(hi));
    return d;
}
__device__ __forceinline__ void unpack2(u64 v, float& lo, float& hi) {
    asm("mov.b64 {%0, %1}, %2;" : "=f"(lo), "=f"(hi) : "l"(v));
}
__device__ __forceinline__ float rcp_approx(float x) {
    float y; asm("rcp.approx.f32 %0, %1;" : "=f"(y) : "f"(x));
    return y;
}

// ---------------------------------------------------------------------------
// Kernel 1: per-(chunk, model) "gain" partial sums.
// Thread = model; inner loop walks 64 point-PAIRS held packed in shared.
// All lanes read the same pair -> LDS broadcast. Gain formulation:
//   gain = max( min(4 - d2, BIG*pz), 0 )   ( == 4 - clip_score, gated by pz>0 )
// so score(model) = 4*N - sum(gain). Branch-free, fully packed f32x2.
// ---------------------------------------------------------------------------
__global__ __launch_bounds__(THREADS)
void p3p_score_kernel(const float* __restrict__ X,       // (N,4) homogeneous
                      const float* __restrict__ x,       // (N,3) homogeneous
                      const float* __restrict__ models)  // (B,3,4)
{
    // Pair-packed tiles: each u64 holds {pt0, pt1} floats, ready as f32x2.
    __shared__ ulonglong2 sA[PAIRS];   // .x = {Xx0,Xx1}   .y = {Xy0,Xy1}
    __shared__ ulonglong2 sB[PAIRS];   // .x = {Xz0,Xz1}   .y = {-xx0,-xx1}
    __shared__ u64        sC[PAIRS];   //      {-xy0,-xy1}

    const int t     = threadIdx.x;
    const int mblk  = blockIdx.x;        // 0..7
    const int chunk = blockIdx.y;        // 0..63
    const int n0    = chunk * TILE;

    if (t < TILE) {
        const int n = n0 + t;
        const int j = t >> 1, h = t & 1;
        float4 X4 = *reinterpret_cast<const float4*>(X + 4 * n);  // w == 1
        const float xx = x[3 * n + 0];
        const float xy = x[3 * n + 1];
        float* fA = reinterpret_cast<float*>(sA);
        float* fB = reinterpret_cast<float*>(sB);
        float* fC = reinterpret_cast<float*>(sC);
        fA[4 * j + h]     = X4.x;
        fA[4 * j + 2 + h] = X4.y;
        fB[4 * j + h]     = X4.z;
        fB[4 * j + 2 + h] = -xx;
        fC[2 * j + h]     = -xy;
    }
    __syncthreads();

    // Model coefficients, broadcast-packed {m,m} once (12 reg pairs).
    const int m = mblk * THREADS + t;
    const float4 r0 = *reinterpret_cast<const float4*>(models + 12 * m + 0);
    const float4 r1 = *reinterpret_cast<const float4*>(models + 12 * m + 4);
    const float4 r2 = *reinterpret_cast<const float4*>(models + 12 * m + 8);
    const u64 M00 = pack2(r0.x, r0.x), M01 = pack2(r0.y, r0.y);
    const u64 M02 = pack2(r0.z, r0.z), M03 = pack2(r0.w, r0.w);
    const u64 M10 = pack2(r1.x, r1.x), M11 = pack2(r1.y, r1.y);
    const u64 M12 = pack2(r1.z, r1.z), M13 = pack2(r1.w, r1.w);
    const u64 M20 = pack2(r2.x, r2.x), M21 = pack2(r2.y, r2.y);
    const u64 M22 = pack2(r2.z, r2.z), M23 = pack2(r2.w, r2.w);
    const u64 NEG4_2 = pack2(-INL_TH_SQ, -INL_TH_SQ);
    const u64 BIG2   = pack2(BIG_GATE, BIG_GATE);

    float acc0 = 0.0f, acc1 = 0.0f;   // two chains: no FADD serialization

    #pragma unroll 8
    for (int j = 0; j < PAIRS; ++j) {
        const ulonglong2 A = sA[j];
        const ulonglong2 B = sB[j];
        const u64        C = sC[j];

        const u64 pz2 = fma2(M20, A.x, fma2(M21, A.y, fma2(M22, B.x, M23)));
        const u64 px2 = fma2(M00, A.x, fma2(M01, A.y, fma2(M02, B.x, M03)));
        const u64 py2 = fma2(M10, A.x, fma2(M11, A.y, fma2(M12, B.x, M13)));

        float zl, zh; unpack2(pz2, zl, zh);
        const u64 inv2 = pack2(rcp_approx(zl), rcp_approx(zh));

        const u64 dx2 = fma2(px2, inv2, B.y);       // px/pz - xx
        const u64 dy2 = fma2(py2, inv2, C);         // py/pz - xy
        const u64 t2  = fma2(dy2, dy2, NEG4_2);     // dy^2 - 4
        const u64 v2  = fma2(dx2, dx2, t2);         // dx^2 + dy^2 - 4
        const u64 c2  = mul2(pz2, BIG2);            // chirality gate

        float vl, vh, cl, ch;
        unpack2(v2, vl, vh);
        unpack2(c2, cl, ch);
        acc0 += fmaxf(fminf(-vl, cl), 0.0f);
        acc1 += fmaxf(fminf(-vh, ch), 0.0f);
    }
    g_part[chunk][m] = acc0 + acc1;
}

// ---------------------------------------------------------------------------
// Kernel 2: finish per-model gains. Thread = model, fixed-order chunk sum.
// Coalesced loads (consecutive threads hit consecutive g_part columns),
// spread over 8 blocks / 8 SMs.
// ---------------------------------------------------------------------------
__global__ __launch_bounds__(THREADS)
void p3p_reduce_kernel()
{
    const int m = blockIdx.x * THREADS + threadIdx.x;
    float s0 = 0.0f, s1 = 0.0f;
    #pragma unroll
    for (int c = 0; c < N_CHUNKS; c += 2) {
        s0 += g_part[c][m];
        s1 += g_part[c + 1][m];
    }
    g_score[m] = s0 + s1;
}

// ---------------------------------------------------------------------------
// Kernel 3: argmax gain over 2048 models (== argmin score; tie -> lowest
// index, matching jnp.argmin). Writes best model + best score + g_best_idx.
// ---------------------------------------------------------------------------
__global__ __launch_bounds__(1024)
void p3p_argmin_kernel(const float* __restrict__ models, float* __restrict__ out)
{
    __shared__ float sv[1024];
    __shared__ int   si[1024];
    __shared__ int   s_best;

    const int t = threadIdx.x;

    float g0 = g_score[t];
    float g1 = g_score[t + 1024];
    float bestg; int besti;
    if (g1 > g0) { bestg = g1; besti = t + 1024; }
    else         { bestg = g0; besti = t; }
    sv[t] = bestg;
    si[t] = besti;
    __syncthreads();

    for (int stride = 512; stride > 0; stride >>= 1) {
        if (t < stride) {
            const float og = sv[t + stride];
            const int   oi = si[t + stride];
            if (og > sv[t] || (og == sv[t] && oi < si[t])) { sv[t] = og; si[t] = oi; }
        }
        __syncthreads();
    }
    if (t == 0) {
        s_best = si[0];
        g_best_idx = si[0];
        out[12 + N_PTS] = INL_TH_SQ * (float)N_PTS - sv[0];   // score = 4N - gain
    }
    __syncthreads();
    if (t < 12)
        out[t] = models[12 * s_best + t];
}

// ---------------------------------------------------------------------------
// Kernel 4: inlier mask for the winning model (exact division, strict test).
// ---------------------------------------------------------------------------
__global__ __launch_bounds__(256)
void p3p_inlier_kernel(const float* __restrict__ X,
                       const float* __restrict__ x,
                       const float* __restrict__ models,
                       float* __restrict__ out)
{
    const int n = blockIdx.x * blockDim.x + threadIdx.x;
    const int bi = g_best_idx;
    const float* M = models + 12 * bi;

    float4 X4 = *reinterpret_cast<const float4*>(X + 4 * n);
    const float xx = x[3 * n + 0];
    const float xy = x[3 * n + 1];

    const float pz = fmaf(M[8], X4.x, fmaf(M[9],  X4.y, fmaf(M[10], X4.z, M[11])));
    const float px = fmaf(M[0], X4.x, fmaf(M[1],  X4.y, fmaf(M[2],  X4.z, M[3])));
    const float py = fmaf(M[4], X4.x, fmaf(M[5],  X4.y, fmaf(M[6],  X4.z, M[7])));
    const float inv = 1.0f / pz;                 // exact
    const float dx = fmaf(px, inv, -xx);
    const float dy = fmaf(py, inv, -xy);
    const float d2 = fmaf(dx, dx, dy * dy);

    out[12 + n] = (pz > 0.0f && d2 < INL_TH_SQ) ? 1.0f : 0.0f;
}

// ---------------------------------------------------------------------------
extern "C" void kernel_launch(void* const* d_in, const int* in_sizes, int n_in,
                              void* d_out, int out_size)
{
    const float* X      = (const float*)d_in[0];   // (8192, 4)
    const float* x      = (const float*)d_in[1];   // (8192, 3)
    const float* models = (const float*)d_in[2];   // (2048, 3, 4)
    float* out = (float*)d_out;                    // 12 + 8192 + 1 floats

    (void)in_sizes; (void)n_in; (void)out_size;

    dim3 grid1(N_MBLK, N_CHUNKS);                  // 8 x 64 = 512 blocks
    p3p_score_kernel<<<grid1, THREADS>>>(X, x, models);
    p3p_reduce_kernel<<<N_MBLK, THREADS>>>();
    p3p_argmin_kernel<<<1, 1024>>>(models, out);
    p3p_inlier_kernel<<<N_PTS / 256, 256>>>(X, x, models, out);
}